// round 9
// baseline (speedup 1.0000x reference)
#include <cuda_runtime.h>
#include <cstdint>
#include <cstddef>

// HugeNet: 10000 x (Linear(100,100)+ReLU) scan, then Linear(100,10).
//
// Round 9: instruction-count attack on the R3 skeleton.
//  - 64 CTAs x 4 rows, 256 threads.
//  - warp w: kq = w&3 (k-group, warp-uniform -> compile-time-specialized
//    7-quad / 6-quad unrolled bodies, no predication), m = (w>>2)*32+lane
//    (column pair, m<50 live; balanced across SMSPs).
//  - k-groups exact: bases {0,28,52,76}, widths {28,24,24,24}.
//  - W: thread-interleaved fp32 layout, one running byte pointer +
//    immediate slot offsets (4096B); double-buffered in registers.
//  - reduction: red[kq][jj*4+r][m] in smem; phase-2 fully parallel
//    (200 threads x 2 outputs, 8 LDS each). Two barriers/layer.

#define N_LAYERS 10000
#define D        100
#define D_OUT    10
#define NCTA     64
#define THREADS  256
#define SLOTS    14                     // slot capacity per thread per layer
#define LSTRIDE  (SLOTS * THREADS)      // float4 per layer = 3584
#define LBYTES   (LSTRIDE * 16)         // 57344 bytes per layer

typedef unsigned long long ull;

// [(N_LAYERS+2)][SLOTS][256] float4  (~574MB, zero-padded)
__device__ __align__(16) float4 g_Wp[(size_t)(N_LAYERS + 2) * LSTRIDE];

__host__ __device__ __forceinline__ int kqb(int kq) {
    return kq ? (28 + 24 * (kq - 1)) : 0;     // {0,28,52,76}
}
__host__ __device__ __forceinline__ int kqn(int kq) {
    return kq ? 6 : 7;                        // widths {28,24,24,24}
}

// ---------------------------------------------------------------------------
// prep: W[l][j][k] row-major -> g_Wp[(l*SLOTS + i)*256 + t]
//   t: lane=t&31, w=t>>5, kq=w&3, m=(w>>2)*32+lane
//   i = 2q+jj; j = 2m+jj; k = kqb(kq)+4q; zero if q>=kqn or j>=100 or pad l.
// ---------------------------------------------------------------------------
__global__ void prep_kernel(const float* __restrict__ W) {
    size_t idx = (size_t)blockIdx.x * blockDim.x + threadIdx.x;
    const size_t total = (size_t)(N_LAYERS + 2) * LSTRIDE;
    if (idx >= total) return;
    int    t    = (int)(idx & (THREADS - 1));
    size_t rest = idx >> 8;
    int    i    = (int)(rest % SLOTS);
    size_t l    = rest / SLOTS;
    int lane = t & 31, w = t >> 5;
    int kq = w & 3;
    int m  = ((w >> 2) << 5) | lane;
    int jj = i & 1, q = i >> 1;
    int j  = 2 * m + jj;
    int k  = kqb(kq) + 4 * q;
    float4 v = make_float4(0.f, 0.f, 0.f, 0.f);
    if (l < N_LAYERS && j < D && q < kqn(kq))
        v = *reinterpret_cast<const float4*>(
                W + l * (size_t)(D * D) + (size_t)j * D + k);
    g_Wp[idx] = v;
}

// ---------------------------------------------------------------------------
__device__ __forceinline__ void fma2(ull& a, ull x, ull y) {
    asm("fma.rn.f32x2 %0, %1, %2, %0;" : "+l"(a) : "l"(x), "l"(y));
}
__device__ __forceinline__ float2 upk(ull v) {
    float2 r;
    asm("mov.b64 {%0, %1}, %2;" : "=f"(r.x), "=f"(r.y) : "l"(v));
    return r;
}

__global__ void __launch_bounds__(THREADS, 1)
hugenet_kernel(const float* __restrict__ x,
               const float* __restrict__ bg,
               const float* __restrict__ Wo,
               const float* __restrict__ bo,
               float* __restrict__ out) {
    __shared__ float h[2][4][D];          // 3.2KB; row stride 400B (16B mult)
    __shared__ float red[4][8][64];       // 8KB [kq][jj*4+r][m]

    const int tid  = threadIdx.x;
    const int lane = tid & 31, w = tid >> 5;
    const int kq   = w & 3;
    const int m    = ((w >> 2) << 5) | lane;
    const bool live = (m < 50);
    const float* hk_base[2] = { &h[0][0][0] + kqb(kq), &h[1][0][0] + kqb(kq) };

    const bool p2live = (tid < 200);
    const int  r2 = tid / 50, jp = tid % 50;

    const int r0 = blockIdx.x * 4;

    for (int idx = tid; idx < 4 * D; idx += THREADS)
        h[0][idx / D][idx % D] = x[(size_t)(r0 + idx / D) * D + idx % D];
    __syncthreads();

    float4 Wa[SLOTS], Wb[SLOTS];
    float2 pba = make_float2(0.f, 0.f), pbb = pba;

    const char* wptr = reinterpret_cast<const char*>(g_Wp) + (size_t)tid * 16;

    auto ldW = [&](float4* R, size_t l) {
        if (!live) return;
        const char* p = wptr + l * (size_t)LBYTES;
        if (kq == 0) {
            #pragma unroll
            for (int i = 0; i < 14; i++)
                R[i] = __ldg(reinterpret_cast<const float4*>(p + i * 4096));
        } else {
            #pragma unroll
            for (int i = 0; i < 12; i++)
                R[i] = __ldg(reinterpret_cast<const float4*>(p + i * 4096));
        }
    };
    auto ldPB = [&](float2& bb, int l) {
        if (p2live && l < N_LAYERS)
            bb = *reinterpret_cast<const float2*>(bg + (size_t)l * D + 2 * jp);
    };

    // phase 1: partial dots for cols (2m, 2m+1), rows 0..3, this k-group
    auto phase1 = [&](const float4* R, int HB) {
        if (live) {
            ull a[8] = {0ull,0ull,0ull,0ull,0ull,0ull,0ull,0ull};
            const float* hk = hk_base[HB];
            if (kq == 0) {
                #pragma unroll
                for (int q = 0; q < 7; q++) {
                    ulonglong2 w0 = *reinterpret_cast<const ulonglong2*>(&R[2*q]);
                    ulonglong2 w1 = *reinterpret_cast<const ulonglong2*>(&R[2*q+1]);
                    #pragma unroll
                    for (int r = 0; r < 4; r++) {
                        ulonglong2 hv = *reinterpret_cast<const ulonglong2*>(
                                            hk + r * D + 4 * q);
                        fma2(a[r],     hv.x, w0.x);
                        fma2(a[r],     hv.y, w0.y);
                        fma2(a[4 + r], hv.x, w1.x);
                        fma2(a[4 + r], hv.y, w1.y);
                    }
                }
            } else {
                #pragma unroll
                for (int q = 0; q < 6; q++) {
                    ulonglong2 w0 = *reinterpret_cast<const ulonglong2*>(&R[2*q]);
                    ulonglong2 w1 = *reinterpret_cast<const ulonglong2*>(&R[2*q+1]);
                    #pragma unroll
                    for (int r = 0; r < 4; r++) {
                        ulonglong2 hv = *reinterpret_cast<const ulonglong2*>(
                                            hk + r * D + 4 * q);
                        fma2(a[r],     hv.x, w0.x);
                        fma2(a[r],     hv.y, w0.y);
                        fma2(a[4 + r], hv.x, w1.x);
                        fma2(a[4 + r], hv.y, w1.y);
                    }
                }
            }
            #pragma unroll
            for (int i = 0; i < 8; i++) {
                float2 u = upk(a[i]);
                red[kq][i][m] = u.x + u.y;
            }
        }
    };

    // phase 2: 200 threads, output (row r2, cols 2jp, 2jp+1)
    auto phase2 = [&](float2 pb, int HB) {
        if (p2live) {
            float s0 = ((red[0][r2][jp]     + red[1][r2][jp])
                      + (red[2][r2][jp]     + red[3][r2][jp])) + pb.x;
            float s1 = ((red[0][4 + r2][jp] + red[1][4 + r2][jp])
                      + (red[2][4 + r2][jp] + red[3][4 + r2][jp])) + pb.y;
            *reinterpret_cast<float2*>(&h[HB ^ 1][r2][2 * jp]) =
                make_float2(fmaxf(s0, 0.f), fmaxf(s1, 0.f));
        }
    };

    ldW(Wa, 0);  ldW(Wb, 1);
    ldPB(pba, 0); ldPB(pbb, 1);

    #pragma unroll 1
    for (int l = 0; l < N_LAYERS; l += 2) {
        // ---- layer l: h[0] -> h[1] ----
        phase1(Wa, 0);
        float2 pb0 = pba;
        ldW(Wa, (size_t)l + 2); ldPB(pba, l + 2);   // pad layers zeroed
        __syncthreads();
        phase2(pb0, 0);
        __syncthreads();

        // ---- layer l+1: h[1] -> h[0] ----
        phase1(Wb, 1);
        float2 pb1 = pbb;
        ldW(Wb, (size_t)l + 3); ldPB(pbb, l + 3);
        __syncthreads();
        phase2(pb1, 1);
        __syncthreads();
    }

    // Final Linear(100, 10): 40 threads, one (row, out-col). h in h[0].
    if (tid < 4 * D_OUT) {
        int r = tid / D_OUT, o = tid % D_OUT;
        const float* hr = h[0][r];
        float acc = bo[o];
        #pragma unroll
        for (int k = 0; k < D; k++)
            acc += hr[k] * __ldg(&Wo[(size_t)o * D + k]);
        out[(size_t)(r0 + r) * D_OUT + o] = acc;
    }
}

// ---------------------------------------------------------------------------
extern "C" void kernel_launch(void* const* d_in, const int* in_sizes, int n_in,
                              void* d_out, int out_size) {
    const float *x = nullptr, *W = nullptr, *b = nullptr, *Wo = nullptr, *bo = nullptr;
    for (int i = 0; i < n_in; i++) {
        switch (in_sizes[i]) {
            case 25600:     x  = (const float*)d_in[i]; break;
            case 100000000: W  = (const float*)d_in[i]; break;
            case 1000000:   b  = (const float*)d_in[i]; break;
            case 1000:      Wo = (const float*)d_in[i]; break;
            case 10:        bo = (const float*)d_in[i]; break;
            default: break;
        }
    }

    const size_t total = (size_t)(N_LAYERS + 2) * LSTRIDE;
    int blocks = (int)((total + 255) / 256);
    prep_kernel<<<blocks, 256>>>(W);

    hugenet_kernel<<<NCTA, THREADS>>>(x, b, Wo, bo, (float*)d_out);
}